// round 11
// baseline (speedup 1.0000x reference)
#include <cuda_runtime.h>
#include <cstdint>

#define D_BINS 59
#define C_CH   80
#define O_TOT  139
#define B_     4
#define N_     6
#define CIN    256
#define H_     16
#define W_     44
#define HW     704              // H_*W_
#define NPIX   (B_*N_*H_*W_)    // 16896 = 264 * 64
#define NCELL  (B_*128*128)     // 65536
#define BEVW   128
#define NPAIR  (D_BINS*W_)      // 2596 (d,w) pairs per row
#define CAP    64               // bin capacity: Poisson(15.2), P(>=64)~1e-28/cell — safe
#define STAGE  32               // records staged in smem per cell in gather
#define GCELLS 32               // cells per gather block
#define OT3    48               // outputs per o-third

// packed fp32x2 FMA (SASS FFMA2): 2 FMAs per instruction, exact fp32 math
#define FMA_F32X2(d, a, b, c) \
    asm("fma.rn.f32x2 %0, %1, %2, %3;" : "=l"(d) : "l"(a), "l"(b), "l"(c))
#define PACK_F32X2(out, lo, hi) \
    asm("mov.b64 %0, {%1, %2};" : "=l"(out) : "f"(lo), "f"(hi))
#define UNPACK_F32X2(lo, hi, in) \
    asm("mov.b64 {%0, %1}, %2;" : "=f"(lo), "=f"(hi) : "l"(in))

// ---- device scratch (no allocations; zero-initialized at load) ----
__device__ float g_dep[NPIX*64];           // [pix][o<59] depth logits, 4.3 MB
__device__ float g_ctx[NPIX*C_CH];         // [pix][c] fp32 ctx, 5.4 MB (L2-resident)
__device__ int   g_cnt[NCELL];             // per-cell counts (reset by gather)
__device__ int2  g_bin[NCELL*CAP];         // {pix, depth-bits}, 33.5 MB

// ============================================================================
// K1: GEMM. Block = (64-px strip, o-third): 48o x 64px x 256c, 128 threads.
// Thread tile 6o x 4px, accumulated as f32x2 PAIRS over the o dimension:
// weights come out of smem as 3 ready-made pairs (float4+float2 LDS), x is
// duplicated into {x,x} pairs (4 mov.b64 on the idle ALU pipe). Inner loop =
// 3 LDS + 4 packs + 12 FFMA2  (vs 24 FFMA): FMA-pipe cycles halved.
// ============================================================================
__global__ __launch_bounds__(128) void gemm_kernel(
    const float* __restrict__ img, const float* __restrict__ wd,
    const float* __restrict__ bd)
{
    __shared__ float ws[32 * 64];    // [c][o_tile][8], 8 KB (32B-aligned groups)
    __shared__ float xs[32 * 64];    // [c][px]        8 KB
    __shared__ int   s_base[64];     // per-px img base offset

    const int tid   = threadIdx.x;
    const int blk   = blockIdx.x;
    const int pxb   = blk / 3;
    const int third = blk - pxb * 3;
    const int px0   = pxb * 64;
    const int o0    = third * OT3;
    const float4* w4 = (const float4*)wd;   // [139][64] float4

    if (tid < 64) {
        int p  = px0 + tid;
        int bn = p / HW;
        int hw = p - bn * HW;
        s_base[tid] = bn * (CIN * HW) + hw;
    }

    const int pt = tid & 15;   // px-tile (4 px), 16 tiles
    const int ot = tid >> 4;   // o-tile (6 o),   8 tiles

    unsigned long long accp[3][4];   // [o-pair][px], f32x2 packed
#pragma unroll
    for (int j = 0; j < 3; j++)
#pragma unroll
        for (int k = 0; k < 4; k++) accp[j][k] = 0ull;

    for (int ck = 0; ck < 8; ck++) {        // 8 chunks of 32 input channels
        __syncthreads();                    // prev compute done (also covers s_base)
        // stage weights: idx = o_l*8 + c4, o_l < 48
#pragma unroll
        for (int r = 0; r < 3; r++) {
            int idx = tid + 128 * r;
            int o_l = idx >> 3;
            int c4  = idx & 7;
            float4 v = make_float4(0.f, 0.f, 0.f, 0.f);
            if (o0 + o_l < O_TOT) v = w4[(o0 + o_l) * 64 + ck * 8 + c4];
            int otl = o_l / 6;
            int oin = o_l - otl * 6;
            ws[((c4 * 4 + 0) * 8 + otl) * 8 + oin] = v.x;
            ws[((c4 * 4 + 1) * 8 + otl) * 8 + oin] = v.y;
            ws[((c4 * 4 + 2) * 8 + otl) * 8 + oin] = v.z;
            ws[((c4 * 4 + 3) * 8 + otl) * 8 + oin] = v.w;
        }
        // stage x: 32c x 64px, coalesced per c-row
#pragma unroll
        for (int r = 0; r < 16; r++) {
            int i  = tid + 128 * r;
            int c  = i >> 6;
            int px = i & 63;
            xs[i] = img[s_base[px] + (ck * 32 + c) * HW];
        }
        __syncthreads();

#pragma unroll 4
        for (int c = 0; c < 32; c++) {
            const float* wp = &ws[(c * 8 + ot) * 8];
            // 3 weight pairs straight from smem (32B-aligned group)
            unsigned long long wpr[3];
            {
                const unsigned long long* wp64 = (const unsigned long long*)wp;
                wpr[0] = wp64[0];            // part of LDS.128
                wpr[1] = wp64[1];
                wpr[2] = wp64[2];            // LDS.64
            }
            float4 xv = *(const float4*)&xs[c * 64 + pt * 4];  // LDS.128
            unsigned long long xp[4];
            PACK_F32X2(xp[0], xv.x, xv.x);
            PACK_F32X2(xp[1], xv.y, xv.y);
            PACK_F32X2(xp[2], xv.z, xv.z);
            PACK_F32X2(xp[3], xv.w, xv.w);
#pragma unroll
            for (int j = 0; j < 3; j++)
#pragma unroll
                for (int k = 0; k < 4; k++)
                    FMA_F32X2(accp[j][k], wpr[j], xp[k], accp[j][k]);
        }
    }

    // unpack + store: depth logits -> g_dep[pix][o], ctx -> g_ctx[pix][o-59]
#pragma unroll
    for (int j = 0; j < 3; j++) {
#pragma unroll
        for (int k = 0; k < 4; k++) {
            float vlo, vhi;
            UNPACK_F32X2(vlo, vhi, accp[j][k]);
            int p = px0 + pt * 4 + k;
#pragma unroll
            for (int half = 0; half < 2; half++) {
                int o_g = o0 + ot * 6 + j * 2 + half;
                if (o_g < O_TOT) {
                    float v = (half ? vhi : vlo) + __ldg(&bd[o_g]);
                    if (o_g < D_BINS) g_dep[p * 64 + o_g]              = v;
                    else              g_ctx[p * C_CH + (o_g - D_BINS)] = v;
                }
            }
        }
    }
}

// ============================================================================
// K2: softmax(59) over g_dep + cell binning. 384 blocks (one per row) x 256.
// ============================================================================
__global__ __launch_bounds__(256) void softmax_bin_kernel(const int* __restrict__ geom)
{
    __shared__ float s_dep[NPAIR];     // [d][44]
    __shared__ int   s_cell[NPAIR];    // [d][44]

    const int tid = threadIdx.x;
    const int row = blockIdx.x;
    const int bn  = row >> 4;
    const int h   = row & 15;
    const int b   = bn / N_;
    const int pixbase = row * W_;

    // stage geom cells (overlaps softmax loads)
    {
        const int2* g2 = (const int2*)geom;
        const int cbase = bn * D_BINS * HW + h * W_;
        for (int i = tid; i < NPAIR; i += 256) {
            int d = i / W_;
            int w = i - d * W_;
            int2 g = __ldg(&g2[cbase + d * HW + w]);
            s_cell[i] = (b << 14) + g.x * BEVW + g.y;
        }
    }

    // softmax: one warp per w-column
    const int warp = tid >> 5;
    const int lane = tid & 31;
    for (int w = warp; w < W_; w += 8) {
        const float* dp = &g_dep[(pixbase + w) * 64];
        float v0 = (lane < D_BINS)        ? __ldg(&dp[lane])      : -1e30f;
        float v1 = ((lane + 32) < D_BINS) ? __ldg(&dp[lane + 32]) : -1e30f;
        float m = fmaxf(v0, v1);
#pragma unroll
        for (int off = 16; off; off >>= 1)
            m = fmaxf(m, __shfl_xor_sync(0xffffffffu, m, off));
        float e0 = (lane < D_BINS)        ? expf(v0 - m) : 0.f;
        float e1 = ((lane + 32) < D_BINS) ? expf(v1 - m) : 0.f;
        float s = e0 + e1;
#pragma unroll
        for (int off = 16; off; off >>= 1)
            s += __shfl_xor_sync(0xffffffffu, s, off);
        float inv = 1.0f / s;
        if (lane < D_BINS)        s_dep[lane * W_ + w]        = e0 * inv;
        if ((lane + 32) < D_BINS) s_dep[(lane + 32) * W_ + w] = e1 * inv;
    }
    __syncthreads();

    // bin the 2596 points
    for (int p = tid; p < NPAIR; p += 256) {
        int w = p % W_;
        int cell = s_cell[p];
        int slot = atomicAdd(&g_cnt[cell], 1);
        if (slot < CAP)
            g_bin[cell * CAP + slot] =
                make_int2(pixbase + w, __float_as_int(s_dep[p]));
    }
}

// ============================================================================
// K3: GATHER per BEV cell. 2048 blocks x 128 threads; block = 32 cells,
// warp = 8 cells. Records staged in smem unconditionally; point loop in
// chunks of 8 -> 8 independent LDG.128 in flight per warp (MLP 8).
// 12 blocks/SM (smem-limited) -> 75% occupancy to soak residual latency.
// cnt>32 tail (P~9e-5/cell) reads gmem directly.
// ============================================================================
__global__ __launch_bounds__(128, 12) void gather_kernel(float* __restrict__ out)
{
    __shared__ int2  s_rec[GCELLS * STAGE];      // 8 KB
    __shared__ int   s_cnt[GCELLS];
    __shared__ float t[C_CH * (GCELLS + 1)];     // [c][33] 10.6 KB

    const int tid  = threadIdx.x;
    const int warp = tid >> 5;
    const int lane = tid & 31;
    const int b    = blockIdx.x >> 9;            // 512 blocks per batch
    const int yx0  = (blockIdx.x & 511) * GCELLS;
    const int cell0 = (b << 14) + yx0;
    const float4* ctx4 = (const float4*)g_ctx;

    if (tid < GCELLS) {
        int c = g_cnt[cell0 + tid];
        g_cnt[cell0 + tid] = 0;                  // reset for next graph replay
        s_cnt[tid] = (c > CAP) ? CAP : c;
    }
#pragma unroll
    for (int r = 0; r < GCELLS * STAGE / 128; r++) {
        int i  = tid + 128 * r;                  // i = cl*32 + slot
        int cl = i >> 5, slot = i & 31;
        s_rec[i] = g_bin[(cell0 + cl) * CAP + slot];
    }
    __syncthreads();

#pragma unroll
    for (int cc = 0; cc < 8; cc++) {
        const int cl  = warp * 8 + cc;           // local cell 0..31
        const int cnt = s_cnt[cl];
        const int cnt_s = (cnt < STAGE) ? cnt : STAGE;
        const int2* rec = &s_rec[cl * STAGE];

        float4 acc = make_float4(0.f, 0.f, 0.f, 0.f);
        for (int base = 0; base < cnt_s; base += 8) {
            int   pix[8];
            float dep[8];
#pragma unroll
            for (int u = 0; u < 8; u++) {
                int pt  = base + u;
                int idx = (pt < cnt_s) ? pt : (cnt_s - 1);
                int2 rr = rec[idx];              // LDS broadcast
                pix[u] = rr.x;
                dep[u] = (pt < cnt_s) ? __int_as_float(rr.y) : 0.f;
            }
            if (lane < 20) {
#pragma unroll
                for (int u = 0; u < 8; u++) {
                    float4 cv = __ldg(&ctx4[pix[u] * 20 + lane]);
                    acc.x += dep[u] * cv.x;
                    acc.y += dep[u] * cv.y;
                    acc.z += dep[u] * cv.z;
                    acc.w += dep[u] * cv.w;
                }
            }
        }
        // rare overflow tail
        for (int pt = STAGE; pt < cnt; pt++) {
            int2 rr = __ldg(&g_bin[(cell0 + cl) * CAP + pt]);
            float dep0 = __int_as_float(rr.y);
            if (lane < 20) {
                float4 cv = __ldg(&ctx4[rr.x * 20 + lane]);
                acc.x += dep0 * cv.x; acc.y += dep0 * cv.y;
                acc.z += dep0 * cv.z; acc.w += dep0 * cv.w;
            }
        }
        if (lane < 20) {
            int c = lane * 4;
            t[(c + 0) * (GCELLS + 1) + cl] = acc.x;
            t[(c + 1) * (GCELLS + 1) + cl] = acc.y;
            t[(c + 2) * (GCELLS + 1) + cl] = acc.z;
            t[(c + 3) * (GCELLS + 1) + cl] = acc.w;
        }
    }
    __syncthreads();

    float* dst = out + ((size_t)b * C_CH) * (128 * 128) + yx0;
#pragma unroll
    for (int i = tid; i < C_CH * GCELLS; i += 128) {
        int c = i >> 5;
        int j = i & 31;
        dst[(size_t)c * (128 * 128) + j] = t[c * (GCELLS + 1) + j];
    }
}

// ============================================================================
extern "C" void kernel_launch(void* const* d_in, const int* in_sizes, int n_in,
                              void* d_out, int out_size)
{
    const float* img  = (const float*)d_in[0];
    const float* wd   = (const float*)d_in[4];
    const float* bd   = (const float*)d_in[5];
    const int*   geom = (const int*)d_in[6];
    float* out = (float*)d_out;

    gemm_kernel<<<(NPIX / 64) * 3, 128>>>(img, wd, bd);
    softmax_bin_kernel<<<B_ * N_ * H_, 256>>>(geom);
    gather_kernel<<<2048, 128>>>(out);
}

// round 13
// speedup vs baseline: 1.3975x; 1.3975x over previous
#include <cuda_runtime.h>
#include <cuda_bf16.h>
#include <mma.h>
#include <cstdint>

using namespace nvcuda;

#define D_BINS 59
#define C_CH   80
#define O_TOT  139
#define B_     4
#define N_     6
#define CIN    256
#define H_     16
#define W_     44
#define HW     704              // H_*W_
#define NPIX   (B_*N_*H_*W_)    // 16896 = 132 * 128
#define NCELL  (B_*128*128)     // 65536
#define BEVW   128
#define NPAIR  (D_BINS*W_)      // 2596
#define CAP    64               // Poisson(15.2), P(>=64)~1e-28/cell — safe
#define STAGE  32
#define GCELLS 32
#define NOUT   144              // padded N (139 -> 144, mult of 48)
#define KC     32               // K-chunk
#define ASTR   40               // smem stride (bf16 elems), 80B = 16B-multiple
#define BSTR   40

// ---- device scratch (no allocations; zero-initialized at load) ----
__device__ float g_dep[NPIX*64];           // [pix][o<59] depth logits, 4.3 MB
__device__ float g_ctx[NPIX*C_CH];         // [pix][c] fp32 ctx, 5.4 MB (L2-resident)
__device__ int   g_cnt[NCELL];             // per-cell counts (reset by gather)
__device__ int2  g_bin[NCELL*CAP];         // {pix, depth-bits}, 33.5 MB

// ============================================================================
// K1: wmma bf16-split GEMM (compute_103-portable tensor path; tcgen05 is
// sm_103a-only and this harness compiles via compute_103 — R12 lesson).
// CTA = 128px x 144o x K256, 384 thr = 12 warps (4M x 3N), warp tile 32x48.
// D = Xh*Wh + Xh*Wl + Xl*Wh  (bf16 hi/lo split, fp32 accum, err ~1.5e-5).
// ============================================================================
__global__ __launch_bounds__(384) void gemm_tc_kernel(
    const float* __restrict__ img, const float* __restrict__ wd,
    const float* __restrict__ bd)
{
    __shared__ __align__(16) char smem_buf[43520];
    __nv_bfloat16* sAh = (__nv_bfloat16*)smem_buf;            // 128*40*2 = 10240
    __nv_bfloat16* sAl = sAh + 128 * ASTR;                    // +10240
    __nv_bfloat16* sBh = (__nv_bfloat16*)(smem_buf + 20480);  // 144*40*2 = 11520
    __nv_bfloat16* sBl = sBh + NOUT * BSTR;                   // +11520 = 43520
    float* scr = (float*)smem_buf;                            // epilogue reuse

    const int tid  = threadIdx.x;
    const int warp = tid >> 5;
    const int lane = tid & 31;
    const int wm   = warp & 3;        // 0..3  (M)
    const int wn   = warp >> 2;       // 0..2  (N)
    const int px0  = blockIdx.x * 128;

    wmma::fragment<wmma::accumulator, 16, 16, 16, float> cf[2][3];
#pragma unroll
    for (int mt = 0; mt < 2; mt++)
#pragma unroll
        for (int nt = 0; nt < 3; nt++) wmma::fill_fragment(cf[mt][nt], 0.f);

    for (int ck = 0; ck < 8; ck++) {
        __syncthreads();
        // ---- stage A: 128 px x 32 c (global coalesced along px) ----
#pragma unroll
        for (int r = 0; r < 11; r++) {
            int i = tid + 384 * r;
            if (i < 128 * KC) {
                int c    = i >> 7;
                int px_l = i & 127;
                int px = px0 + px_l;
                int bn = px / HW;
                int hw = px - bn * HW;
                float x = __ldg(&img[(size_t)bn * CIN * HW + (ck * KC + c) * HW + hw]);
                __nv_bfloat16 h = __float2bfloat16(x);
                __nv_bfloat16 l = __float2bfloat16(x - __bfloat162float(h));
                sAh[px_l * ASTR + c] = h;
                sAl[px_l * ASTR + c] = l;
            }
        }
        // ---- stage B: 144 o x 32 c (global coalesced along c) ----
#pragma unroll
        for (int r = 0; r < 12; r++) {
            int i = tid + 384 * r;
            if (i < NOUT * KC) {
                int n = i >> 5;
                int c = i & 31;
                float w = (n < O_TOT) ? __ldg(&wd[n * CIN + ck * KC + c]) : 0.f;
                __nv_bfloat16 h = __float2bfloat16(w);
                __nv_bfloat16 l = __float2bfloat16(w - __bfloat162float(h));
                sBh[n * BSTR + c] = h;
                sBl[n * BSTR + c] = l;
            }
        }
        __syncthreads();

        // ---- compute: 2 k-steps x 3 terms x (2m x 3n) tiles ----
#pragma unroll
        for (int ks = 0; ks < 2; ks++) {
            wmma::fragment<wmma::matrix_a, 16, 16, 16, __nv_bfloat16, wmma::row_major> ah[2], al[2];
#pragma unroll
            for (int mt = 0; mt < 2; mt++) {
                const int arow = wm * 32 + mt * 16;
                wmma::load_matrix_sync(ah[mt], &sAh[arow * ASTR + ks * 16], ASTR);
                wmma::load_matrix_sync(al[mt], &sAl[arow * ASTR + ks * 16], ASTR);
            }
#pragma unroll
            for (int nt = 0; nt < 3; nt++) {
                const int brow = wn * 48 + nt * 16;
                wmma::fragment<wmma::matrix_b, 16, 16, 16, __nv_bfloat16, wmma::col_major> bh, bl;
                wmma::load_matrix_sync(bh, &sBh[brow * BSTR + ks * 16], BSTR);
                wmma::load_matrix_sync(bl, &sBl[brow * BSTR + ks * 16], BSTR);
#pragma unroll
                for (int mt = 0; mt < 2; mt++) {
                    wmma::mma_sync(cf[mt][nt], ah[mt], bh, cf[mt][nt]);
                    wmma::mma_sync(cf[mt][nt], ah[mt], bl, cf[mt][nt]);
                    wmma::mma_sync(cf[mt][nt], al[mt], bh, cf[mt][nt]);
                }
            }
        }
    }

    // ---- epilogue: per-tile smem roundtrip, bias, route to g_dep / g_ctx ----
    __syncthreads();
    float* wscr = scr + warp * 320;    // 16 x 20 tile
#pragma unroll
    for (int mt = 0; mt < 2; mt++) {
#pragma unroll
        for (int nt = 0; nt < 3; nt++) {
            wmma::store_matrix_sync(wscr, cf[mt][nt], 20, wmma::mem_row_major);
            __syncwarp();
#pragma unroll
            for (int e = 0; e < 8; e++) {
                int idx = lane + e * 32;         // 0..255
                int r   = idx >> 4;
                int col = idx & 15;
                int o = wn * 48 + nt * 16 + col;
                int p = px0 + wm * 32 + mt * 16 + r;
                if (o < O_TOT) {
                    float v = wscr[r * 20 + col] + __ldg(&bd[o]);
                    if (o < D_BINS) g_dep[p * 64 + o] = v;
                    else            g_ctx[p * C_CH + (o - D_BINS)] = v;
                }
            }
            __syncwarp();
        }
    }
}

// ============================================================================
// K2: softmax(59) over g_dep + cell binning. 384 blocks (one per row) x 256.
// ============================================================================
__global__ __launch_bounds__(256) void softmax_bin_kernel(const int* __restrict__ geom)
{
    __shared__ float s_dep[NPAIR];
    __shared__ int   s_cell[NPAIR];

    const int tid = threadIdx.x;
    const int row = blockIdx.x;
    const int bn  = row >> 4;
    const int h   = row & 15;
    const int b   = bn / N_;
    const int pixbase = row * W_;

    {
        const int2* g2 = (const int2*)geom;
        const int cbase = bn * D_BINS * HW + h * W_;
        for (int i = tid; i < NPAIR; i += 256) {
            int d = i / W_;
            int w = i - d * W_;
            int2 g = __ldg(&g2[cbase + d * HW + w]);
            s_cell[i] = (b << 14) + g.x * BEVW + g.y;
        }
    }

    const int warp = tid >> 5;
    const int lane = tid & 31;
    for (int w = warp; w < W_; w += 8) {
        const float* dp = &g_dep[(pixbase + w) * 64];
        float v0 = (lane < D_BINS)        ? __ldg(&dp[lane])      : -1e30f;
        float v1 = ((lane + 32) < D_BINS) ? __ldg(&dp[lane + 32]) : -1e30f;
        float m = fmaxf(v0, v1);
#pragma unroll
        for (int off = 16; off; off >>= 1)
            m = fmaxf(m, __shfl_xor_sync(0xffffffffu, m, off));
        float e0 = (lane < D_BINS)        ? expf(v0 - m) : 0.f;
        float e1 = ((lane + 32) < D_BINS) ? expf(v1 - m) : 0.f;
        float s = e0 + e1;
#pragma unroll
        for (int off = 16; off; off >>= 1)
            s += __shfl_xor_sync(0xffffffffu, s, off);
        float inv = 1.0f / s;
        if (lane < D_BINS)        s_dep[lane * W_ + w]        = e0 * inv;
        if ((lane + 32) < D_BINS) s_dep[(lane + 32) * W_ + w] = e1 * inv;
    }
    __syncthreads();

    for (int p = tid; p < NPAIR; p += 256) {
        int w = p % W_;
        int cell = s_cell[p];
        int slot = atomicAdd(&g_cnt[cell], 1);
        if (slot < CAP)
            g_bin[cell * CAP + slot] =
                make_int2(pixbase + w, __float_as_int(s_dep[p]));
    }
}

// ============================================================================
// K3: GATHER per BEV cell (best config from R10: 8 blocks/SM).
// 2048 blocks x 128 threads; block = 32 cells, warp = 8 cells; point loop in
// chunks of 8 -> 8 independent LDG.128 in flight; cnt>32 tail reads gmem.
// ============================================================================
__global__ __launch_bounds__(128, 8) void gather_kernel(float* __restrict__ out)
{
    __shared__ int2  s_rec[GCELLS * STAGE];
    __shared__ int   s_cnt[GCELLS];
    __shared__ float t[C_CH * (GCELLS + 1)];

    const int tid  = threadIdx.x;
    const int warp = tid >> 5;
    const int lane = tid & 31;
    const int b    = blockIdx.x >> 9;
    const int yx0  = (blockIdx.x & 511) * GCELLS;
    const int cell0 = (b << 14) + yx0;
    const float4* ctx4 = (const float4*)g_ctx;

    if (tid < GCELLS) {
        int c = g_cnt[cell0 + tid];
        g_cnt[cell0 + tid] = 0;
        s_cnt[tid] = (c > CAP) ? CAP : c;
    }
#pragma unroll
    for (int r = 0; r < GCELLS * STAGE / 128; r++) {
        int i  = tid + 128 * r;
        int cl = i >> 5, slot = i & 31;
        s_rec[i] = g_bin[(cell0 + cl) * CAP + slot];
    }
    __syncthreads();

#pragma unroll
    for (int cc = 0; cc < 8; cc++) {
        const int cl  = warp * 8 + cc;
        const int cnt = s_cnt[cl];
        const int cnt_s = (cnt < STAGE) ? cnt : STAGE;
        const int2* rec = &s_rec[cl * STAGE];

        float4 acc = make_float4(0.f, 0.f, 0.f, 0.f);
        for (int base = 0; base < cnt_s; base += 8) {
            int   pix[8];
            float dep[8];
#pragma unroll
            for (int u = 0; u < 8; u++) {
                int pt  = base + u;
                int idx = (pt < cnt_s) ? pt : (cnt_s - 1);
                int2 rr = rec[idx];
                pix[u] = rr.x;
                dep[u] = (pt < cnt_s) ? __int_as_float(rr.y) : 0.f;
            }
            if (lane < 20) {
#pragma unroll
                for (int u = 0; u < 8; u++) {
                    float4 cv = __ldg(&ctx4[pix[u] * 20 + lane]);
                    acc.x += dep[u] * cv.x;
                    acc.y += dep[u] * cv.y;
                    acc.z += dep[u] * cv.z;
                    acc.w += dep[u] * cv.w;
                }
            }
        }
        for (int pt = STAGE; pt < cnt; pt++) {
            int2 rr = __ldg(&g_bin[(cell0 + cl) * CAP + pt]);
            float dep0 = __int_as_float(rr.y);
            if (lane < 20) {
                float4 cv = __ldg(&ctx4[rr.x * 20 + lane]);
                acc.x += dep0 * cv.x; acc.y += dep0 * cv.y;
                acc.z += dep0 * cv.z; acc.w += dep0 * cv.w;
            }
        }
        if (lane < 20) {
            int c = lane * 4;
            t[(c + 0) * (GCELLS + 1) + cl] = acc.x;
            t[(c + 1) * (GCELLS + 1) + cl] = acc.y;
            t[(c + 2) * (GCELLS + 1) + cl] = acc.z;
            t[(c + 3) * (GCELLS + 1) + cl] = acc.w;
        }
    }
    __syncthreads();

    float* dst = out + ((size_t)b * C_CH) * (128 * 128) + yx0;
#pragma unroll
    for (int i = tid; i < C_CH * GCELLS; i += 128) {
        int c = i >> 5;
        int j = i & 31;
        dst[(size_t)c * (128 * 128) + j] = t[c * (GCELLS + 1) + j];
    }
}

// ============================================================================
extern "C" void kernel_launch(void* const* d_in, const int* in_sizes, int n_in,
                              void* d_out, int out_size)
{
    const float* img  = (const float*)d_in[0];
    const float* wd   = (const float*)d_in[4];
    const float* bd   = (const float*)d_in[5];
    const int*   geom = (const int*)d_in[6];
    float* out = (float*)d_out;

    gemm_tc_kernel<<<NPIX / 128, 384>>>(img, wd, bd);
    softmax_bin_kernel<<<B_ * N_ * H_, 256>>>(geom);
    gather_kernel<<<2048, 128>>>(out);
}

// round 14
// speedup vs baseline: 1.4286x; 1.0222x over previous
#include <cuda_runtime.h>
#include <cuda_bf16.h>
#include <mma.h>
#include <cstdint>

using namespace nvcuda;

#define D_BINS 59
#define C_CH   80
#define O_TOT  139
#define B_     4
#define N_     6
#define CIN    256
#define H_     16
#define W_     44
#define HW     704              // H_*W_
#define NPIX   (B_*N_*H_*W_)    // 16896 = 132 * 128
#define NCELL  (B_*128*128)     // 65536
#define BEVW   128
#define CAP    64               // Poisson(15.2), P(>=64)~1e-28/cell — safe
#define STAGE  32
#define GCELLS 32
#define NOUT   144              // padded N
#define KC     32               // K-chunk
#define ASTR   40               // smem stride (bf16), 80B = 16B-multiple
#define BSTR   40
#define DSTR   61               // s_dep row stride (odd -> bank-spread)

// ---- device scratch (no allocations; zero-initialized at load) ----
__device__ float g_ctx[NPIX*C_CH];         // [pix][c] fp32 ctx, 5.4 MB (L2-resident)
__device__ int   g_cnt[NCELL];             // per-cell counts (reset by gather)
__device__ int2  g_bin[NCELL*CAP];         // {pix, depth-bits}, 33.5 MB

// ============================================================================
// K1: wmma bf16-split GEMM + FUSED softmax(59) + cell binning.
// CTA = 128px x 144o x K256, 384 thr = 12 warps (4M x 3N), warp tile 32x48.
// D = Xh*Wh + Xh*Wl + Xl*Wh (bf16 hi/lo split, fp32 accum, err ~1.5e-5).
// Softmax is over OUTPUT channels (d<59) per pixel -> fully CTA-local:
// depth tiles land in smem, shfl-softmax per pixel, bin the 7552 points
// with coalesced geom reads. g_dep scratch + K2 kernel deleted.
// ============================================================================
__global__ __launch_bounds__(384) void gemm_fused_kernel(
    const float* __restrict__ img, const float* __restrict__ wd,
    const float* __restrict__ bd,  const int*   __restrict__ geom)
{
    __shared__ __align__(16) char smem_buf[46592];
    // staging layout (GEMM phase)
    __nv_bfloat16* sAh = (__nv_bfloat16*)smem_buf;            // 10240
    __nv_bfloat16* sAl = sAh + 128 * ASTR;                    // +10240
    __nv_bfloat16* sBh = (__nv_bfloat16*)(smem_buf + 20480);  // 11520
    __nv_bfloat16* sBl = sBh + NOUT * BSTR;                   // +11520 = 43520
    // epilogue layout (reused after final sync)
    float* scr  = (float*)smem_buf;                           // 12*320*4 = 15360
    float* sdep = (float*)(smem_buf + 15360);                 // 128*61*4 = 31232

    const int tid  = threadIdx.x;
    const int warp = tid >> 5;
    const int lane = tid & 31;
    const int wm   = warp & 3;        // 0..3  (M)
    const int wn   = warp >> 2;       // 0..2  (N)
    const int px0  = blockIdx.x * 128;

    wmma::fragment<wmma::accumulator, 16, 16, 16, float> cf[2][3];
#pragma unroll
    for (int mt = 0; mt < 2; mt++)
#pragma unroll
        for (int nt = 0; nt < 3; nt++) wmma::fill_fragment(cf[mt][nt], 0.f);

    for (int ck = 0; ck < 8; ck++) {
        __syncthreads();
        // ---- stage A: 128 px x 32 c (coalesced along px) ----
#pragma unroll
        for (int r = 0; r < 11; r++) {
            int i = tid + 384 * r;
            if (i < 128 * KC) {
                int c    = i >> 7;
                int px_l = i & 127;
                int px = px0 + px_l;
                int bn = px / HW;
                int hw = px - bn * HW;
                float x = __ldg(&img[(size_t)bn * CIN * HW + (ck * KC + c) * HW + hw]);
                __nv_bfloat16 h = __float2bfloat16(x);
                __nv_bfloat16 l = __float2bfloat16(x - __bfloat162float(h));
                sAh[px_l * ASTR + c] = h;
                sAl[px_l * ASTR + c] = l;
            }
        }
        // ---- stage B: 144 o x 32 c (coalesced along c) ----
#pragma unroll
        for (int r = 0; r < 12; r++) {
            int i = tid + 384 * r;
            if (i < NOUT * KC) {
                int n = i >> 5;
                int c = i & 31;
                float w = (n < O_TOT) ? __ldg(&wd[n * CIN + ck * KC + c]) : 0.f;
                __nv_bfloat16 h = __float2bfloat16(w);
                __nv_bfloat16 l = __float2bfloat16(w - __bfloat162float(h));
                sBh[n * BSTR + c] = h;
                sBl[n * BSTR + c] = l;
            }
        }
        __syncthreads();

        // ---- compute: 2 k-steps x 3 terms x (2m x 3n) tiles ----
#pragma unroll
        for (int ks = 0; ks < 2; ks++) {
            wmma::fragment<wmma::matrix_a, 16, 16, 16, __nv_bfloat16, wmma::row_major> ah[2], al[2];
#pragma unroll
            for (int mt = 0; mt < 2; mt++) {
                const int arow = wm * 32 + mt * 16;
                wmma::load_matrix_sync(ah[mt], &sAh[arow * ASTR + ks * 16], ASTR);
                wmma::load_matrix_sync(al[mt], &sAl[arow * ASTR + ks * 16], ASTR);
            }
#pragma unroll
            for (int nt = 0; nt < 3; nt++) {
                const int brow = wn * 48 + nt * 16;
                wmma::fragment<wmma::matrix_b, 16, 16, 16, __nv_bfloat16, wmma::col_major> bh, bl;
                wmma::load_matrix_sync(bh, &sBh[brow * BSTR + ks * 16], BSTR);
                wmma::load_matrix_sync(bl, &sBl[brow * BSTR + ks * 16], BSTR);
#pragma unroll
                for (int mt = 0; mt < 2; mt++) {
                    wmma::mma_sync(cf[mt][nt], ah[mt], bh, cf[mt][nt]);
                    wmma::mma_sync(cf[mt][nt], ah[mt], bl, cf[mt][nt]);
                    wmma::mma_sync(cf[mt][nt], al[mt], bh, cf[mt][nt]);
                }
            }
        }
    }

    // ---- tile scatter: depth (+bias) -> sdep smem; ctx (+bias) -> g_ctx ----
    __syncthreads();
    float* wscr = scr + warp * 320;    // 16 x 20 tile
#pragma unroll
    for (int mt = 0; mt < 2; mt++) {
#pragma unroll
        for (int nt = 0; nt < 3; nt++) {
            wmma::store_matrix_sync(wscr, cf[mt][nt], 20, wmma::mem_row_major);
            __syncwarp();
#pragma unroll
            for (int e = 0; e < 8; e++) {
                int idx = lane + e * 32;         // 0..255
                int r   = idx >> 4;
                int col = idx & 15;
                int o = wn * 48 + nt * 16 + col;
                int p_l = wm * 32 + mt * 16 + r;
                if (o < O_TOT) {
                    float v = wscr[r * 20 + col] + __ldg(&bd[o]);
                    if (o < D_BINS) sdep[p_l * DSTR + o] = v;
                    else            g_ctx[(px0 + p_l) * C_CH + (o - D_BINS)] = v;
                }
            }
            __syncwarp();
        }
    }
    __syncthreads();

    // ---- softmax in smem: one warp per pixel (12 warps round-robin) ----
    for (int px_l = warp; px_l < 128; px_l += 12) {
        float* dp = &sdep[px_l * DSTR];
        float v0 = (lane < D_BINS)        ? dp[lane]      : -1e30f;
        float v1 = ((lane + 32) < D_BINS) ? dp[lane + 32] : -1e30f;
        float m = fmaxf(v0, v1);
#pragma unroll
        for (int off = 16; off; off >>= 1)
            m = fmaxf(m, __shfl_xor_sync(0xffffffffu, m, off));
        float e0 = (lane < D_BINS)        ? expf(v0 - m) : 0.f;
        float e1 = ((lane + 32) < D_BINS) ? expf(v1 - m) : 0.f;
        float s = e0 + e1;
#pragma unroll
        for (int off = 16; off; off >>= 1)
            s += __shfl_xor_sync(0xffffffffu, s, off);
        float inv = 1.0f / s;
        if (lane < D_BINS)        dp[lane]      = e0 * inv;
        if ((lane + 32) < D_BINS) dp[lane + 32] = e1 * inv;
    }
    __syncthreads();

    // ---- bin the CTA's 7552 points (geom reads coalesced along px) ----
    {
        const int2* g2 = (const int2*)geom;
        for (int i = tid; i < D_BINS * 128; i += 384) {
            int d    = i >> 7;
            int px_l = i & 127;
            int px = px0 + px_l;
            int bn = px / HW;
            int hw = px - bn * HW;
            int b  = bn / N_;
            int2 g = __ldg(&g2[(bn * D_BINS + d) * HW + hw]);
            int cell = (b << 14) + g.x * BEVW + g.y;
            int slot = atomicAdd(&g_cnt[cell], 1);
            if (slot < CAP)
                g_bin[cell * CAP + slot] =
                    make_int2(px, __float_as_int(sdep[px_l * DSTR + d]));
        }
    }
}

// ============================================================================
// K3: GATHER per BEV cell. 2048 blocks x 128 threads; block = 32 cells,
// warp = 8 cells processed as 4 PAIRS: chunk-of-4 per cell -> 8 independent
// LDG.128 in flight while each cell-start latency bubble covers two cells.
// cnt>32 tail (P~9e-5/cell) reads gmem directly.
// ============================================================================
__global__ __launch_bounds__(128, 8) void gather_kernel(float* __restrict__ out)
{
    __shared__ int2  s_rec[GCELLS * STAGE];
    __shared__ int   s_cnt[GCELLS];
    __shared__ float t[C_CH * (GCELLS + 1)];

    const int tid  = threadIdx.x;
    const int warp = tid >> 5;
    const int lane = tid & 31;
    const int b    = blockIdx.x >> 9;
    const int yx0  = (blockIdx.x & 511) * GCELLS;
    const int cell0 = (b << 14) + yx0;
    const float4* ctx4 = (const float4*)g_ctx;

    if (tid < GCELLS) {
        int c = g_cnt[cell0 + tid];
        g_cnt[cell0 + tid] = 0;
        s_cnt[tid] = (c > CAP) ? CAP : c;
    }
#pragma unroll
    for (int r = 0; r < GCELLS * STAGE / 128; r++) {
        int i  = tid + 128 * r;
        int cl = i >> 5, slot = i & 31;
        s_rec[i] = g_bin[(cell0 + cl) * CAP + slot];
    }
    __syncthreads();

#pragma unroll
    for (int cp = 0; cp < 4; cp++) {
        const int cl0 = warp * 8 + cp * 2;
        const int cl1 = cl0 + 1;
        const int cnt0 = s_cnt[cl0];
        const int cnt1 = s_cnt[cl1];
        const int c0s = (cnt0 < STAGE) ? cnt0 : STAGE;
        const int c1s = (cnt1 < STAGE) ? cnt1 : STAGE;
        const int2* rec0 = &s_rec[cl0 * STAGE];
        const int2* rec1 = &s_rec[cl1 * STAGE];
        const int maxc = (c0s > c1s) ? c0s : c1s;

        float4 acc0 = make_float4(0.f, 0.f, 0.f, 0.f);
        float4 acc1 = make_float4(0.f, 0.f, 0.f, 0.f);
        for (int base = 0; base < maxc; base += 4) {
            int   pixA[4], pixB[4];
            float depA[4], depB[4];
#pragma unroll
            for (int u = 0; u < 4; u++) {
                int pt = base + u;
                int2 rA = rec0[(pt < c0s) ? pt : 0];     // LDS broadcast
                int2 rB = rec1[(pt < c1s) ? pt : 0];
                pixA[u] = rA.x;  depA[u] = (pt < c0s) ? __int_as_float(rA.y) : 0.f;
                pixB[u] = rB.x;  depB[u] = (pt < c1s) ? __int_as_float(rB.y) : 0.f;
            }
            if (lane < 20) {
#pragma unroll
                for (int u = 0; u < 4; u++) {
                    float4 cvA = __ldg(&ctx4[pixA[u] * 20 + lane]);
                    float4 cvB = __ldg(&ctx4[pixB[u] * 20 + lane]);
                    acc0.x += depA[u] * cvA.x; acc0.y += depA[u] * cvA.y;
                    acc0.z += depA[u] * cvA.z; acc0.w += depA[u] * cvA.w;
                    acc1.x += depB[u] * cvB.x; acc1.y += depB[u] * cvB.y;
                    acc1.z += depB[u] * cvB.z; acc1.w += depB[u] * cvB.w;
                }
            }
        }
        // rare overflow tails
        for (int pt = STAGE; pt < cnt0; pt++) {
            int2 rr = __ldg(&g_bin[(cell0 + cl0) * CAP + pt]);
            float d0 = __int_as_float(rr.y);
            if (lane < 20) {
                float4 cv = __ldg(&ctx4[rr.x * 20 + lane]);
                acc0.x += d0 * cv.x; acc0.y += d0 * cv.y;
                acc0.z += d0 * cv.z; acc0.w += d0 * cv.w;
            }
        }
        for (int pt = STAGE; pt < cnt1; pt++) {
            int2 rr = __ldg(&g_bin[(cell0 + cl1) * CAP + pt]);
            float d0 = __int_as_float(rr.y);
            if (lane < 20) {
                float4 cv = __ldg(&ctx4[rr.x * 20 + lane]);
                acc1.x += d0 * cv.x; acc1.y += d0 * cv.y;
                acc1.z += d0 * cv.z; acc1.w += d0 * cv.w;
            }
        }
        if (lane < 20) {
            int c = lane * 4;
            t[(c + 0) * (GCELLS + 1) + cl0] = acc0.x;
            t[(c + 1) * (GCELLS + 1) + cl0] = acc0.y;
            t[(c + 2) * (GCELLS + 1) + cl0] = acc0.z;
            t[(c + 3) * (GCELLS + 1) + cl0] = acc0.w;
            t[(c + 0) * (GCELLS + 1) + cl1] = acc1.x;
            t[(c + 1) * (GCELLS + 1) + cl1] = acc1.y;
            t[(c + 2) * (GCELLS + 1) + cl1] = acc1.z;
            t[(c + 3) * (GCELLS + 1) + cl1] = acc1.w;
        }
    }
    __syncthreads();

    float* dst = out + ((size_t)b * C_CH) * (128 * 128) + yx0;
#pragma unroll
    for (int i = tid; i < C_CH * GCELLS; i += 128) {
        int c = i >> 5;
        int j = i & 31;
        dst[(size_t)c * (128 * 128) + j] = t[c * (GCELLS + 1) + j];
    }
}

// ============================================================================
extern "C" void kernel_launch(void* const* d_in, const int* in_sizes, int n_in,
                              void* d_out, int out_size)
{
    const float* img  = (const float*)d_in[0];
    const float* wd   = (const float*)d_in[4];
    const float* bd   = (const float*)d_in[5];
    const int*   geom = (const int*)d_in[6];
    float* out = (float*)d_out;

    gemm_fused_kernel<<<NPIX / 128, 384>>>(img, wd, bd, geom);
    gather_kernel<<<2048, 128>>>(out);
}